// round 13
// baseline (speedup 1.0000x reference)
#include <cuda_runtime.h>

// Problem constants
#define B_  256
#define T_  1024
#define I_  3
#define H_  128
#define O_  3

// ---------------------------------------------------------------------------
// Fast tanh: tanh(x) = 1 - 2/(1 + e^{2x}) via ex2.approx + rcp.approx.
// Limits are exact without clamping. Measured end-to-end rel err ~5e-7.
// ---------------------------------------------------------------------------
__device__ __forceinline__ float fast_tanh(float x) {
    float e;
    asm("ex2.approx.f32 %0, %1;" : "=f"(e) : "f"(x * 2.885390081777927f));
    float rd;
    asm("rcp.approx.f32 %0, %1;" : "=f"(rd) : "f"(1.0f + e));
    return fmaf(-2.0f, rd, 1.0f);
}

// ---------------------------------------------------------------------------
// Recurrent kernel, 2 batches per block (in-thread pairing).
// 128 blocks x 128 threads; thread j owns hidden unit j for BOTH batches
// b0 = 2*bid and b1 = 2*bid+1, reusing the same W_hh row registers.
// Benefits vs 1 batch/block at occupancy 2:
//   - uniform 1 block/SM (no 2-block SMs pacing the chip)
//   - 8 independent FMA chains (2 batches x 4) -> better latency hiding
//   - the serial tanh/store/barrier tail is paid once per 2 batches
// ---------------------------------------------------------------------------
__global__ void __launch_bounds__(H_, 1)
rnn_recurrent_kernel(const float* __restrict__ inputs,   // [B, T, I]
                     const float* __restrict__ W_ih,     // [H, I]
                     const float* __restrict__ W_hh,     // [H, H]
                     const float* __restrict__ b_ih,     // [H]
                     const float* __restrict__ b_hh,     // [H]
                     const float* __restrict__ h0,       // [1, H]
                     float* __restrict__ hiddens)        // [B, T, H]
{
    const int j  = threadIdx.x;
    const int b0 = 2 * blockIdx.x;
    const int b1 = b0 + 1;

    __shared__ float hbuf[2][2][H_];    // [buffer][batch-in-block][unit]

    // W_hh row j -> 128 registers (shared by both batches)
    float w[H_];
    const float4* wrow = reinterpret_cast<const float4*>(W_hh + j * H_);
#pragma unroll
    for (int kk = 0; kk < H_ / 4; ++kk) {
        float4 v = wrow[kk];
        w[4 * kk + 0] = v.x;
        w[4 * kk + 1] = v.y;
        w[4 * kk + 2] = v.z;
        w[4 * kk + 3] = v.w;
    }

    const float wi0  = W_ih[j * I_ + 0];
    const float wi1  = W_ih[j * I_ + 1];
    const float wi2  = W_ih[j * I_ + 2];
    const float bias = b_ih[j] + b_hh[j];

    const float hinit = h0[j];
    hbuf[0][0][j] = hinit;
    hbuf[0][1][j] = hinit;
    __syncthreads();

    const float* in0  = inputs + (size_t)b0 * T_ * I_;
    const float* in1  = inputs + (size_t)b1 * T_ * I_;
    float*       ho0  = hiddens + (size_t)b0 * T_ * H_;
    float*       ho1  = hiddens + (size_t)b1 * T_ * H_;

    float x00 = in0[0], x01 = in0[1], x02 = in0[2];
    float x10 = in1[0], x11 = in1[1], x12 = in1[2];

    int cur = 0;
#pragma unroll 1
    for (int t = 0; t < T_; ++t) {
        // Seed chain 0 of each batch with its input projection
        float a0 = fmaf(x00, wi0, fmaf(x01, wi1, fmaf(x02, wi2, bias)));
        float a1 = 0.f, a2 = 0.f, a3 = 0.f;
        float c0 = fmaf(x10, wi0, fmaf(x11, wi1, fmaf(x12, wi2, bias)));
        float c1 = 0.f, c2 = 0.f, c3 = 0.f;

        // prefetch next x for both batches (off the critical tail)
        {
            const int tn = (t + 1 < T_) ? (t + 1) : (T_ - 1);
            const float* n0 = in0 + tn * I_;
            const float* n1 = in1 + tn * I_;
            x00 = n0[0]; x01 = n0[1]; x02 = n0[2];
            x10 = n1[0]; x11 = n1[1]; x12 = n1[2];
        }

        const float4* h40 = reinterpret_cast<const float4*>(hbuf[cur][0]);
        const float4* h41 = reinterpret_cast<const float4*>(hbuf[cur][1]);
#pragma unroll
        for (int kk = 0; kk < H_ / 4; ++kk) {
            const float4 hv0 = h40[kk];
            const float4 hv1 = h41[kk];
            a0 = fmaf(hv0.x, w[4 * kk + 0], a0);
            a1 = fmaf(hv0.y, w[4 * kk + 1], a1);
            a2 = fmaf(hv0.z, w[4 * kk + 2], a2);
            a3 = fmaf(hv0.w, w[4 * kk + 3], a3);
            c0 = fmaf(hv1.x, w[4 * kk + 0], c0);
            c1 = fmaf(hv1.y, w[4 * kk + 1], c1);
            c2 = fmaf(hv1.z, w[4 * kk + 2], c2);
            c3 = fmaf(hv1.w, w[4 * kk + 3], c3);
        }
        const float accA = (a0 + a1) + (a2 + a3);
        const float accB = (c0 + c1) + (c2 + c3);

        const float hnA = fast_tanh(accA);
        const float hnB = fast_tanh(accB);

        const int nxt = cur ^ 1;
        hbuf[nxt][0][j] = hnA;
        hbuf[nxt][1][j] = hnB;
        ho0[t * H_ + j] = hnA;
        ho1[t * H_ + j] = hnB;
        cur = nxt;
        __syncthreads();
    }
}

// ---------------------------------------------------------------------------
// Output projection: proven config (measured 29.9us).
// One warp per 4 rows, full-warp float4 dot + 5-level SHFL reduction.
// ---------------------------------------------------------------------------
#define ROWS_PER_WARP 4

__global__ void __launch_bounds__(256)
rnn_outproj_kernel(const float* __restrict__ hiddens, // [B*T, H]
                   const float* __restrict__ W_out,   // [O, H]
                   const float* __restrict__ b_out,   // [O]
                   float* __restrict__ out)           // [B*T, O]
{
    const int warp = (blockIdx.x * blockDim.x + threadIdx.x) >> 5;
    const int lane = threadIdx.x & 31;
    const int row0 = warp * ROWS_PER_WARP;
    if (row0 >= B_ * T_) return;

    const float4 w0 = reinterpret_cast<const float4*>(W_out + 0 * H_)[lane];
    const float4 w1 = reinterpret_cast<const float4*>(W_out + 1 * H_)[lane];
    const float4 w2 = reinterpret_cast<const float4*>(W_out + 2 * H_)[lane];
    const float bo0 = b_out[0], bo1 = b_out[1], bo2 = b_out[2];

    float4 hv[ROWS_PER_WARP];
#pragma unroll
    for (int r = 0; r < ROWS_PER_WARP; ++r)
        hv[r] = reinterpret_cast<const float4*>(hiddens + (size_t)(row0 + r) * H_)[lane];

#pragma unroll
    for (int r = 0; r < ROWS_PER_WARP; ++r) {
        float s0 = hv[r].x * w0.x + hv[r].y * w0.y + hv[r].z * w0.z + hv[r].w * w0.w;
        float s1 = hv[r].x * w1.x + hv[r].y * w1.y + hv[r].z * w1.z + hv[r].w * w1.w;
        float s2 = hv[r].x * w2.x + hv[r].y * w2.y + hv[r].z * w2.z + hv[r].w * w2.w;
#pragma unroll
        for (int off = 16; off > 0; off >>= 1) {
            s0 += __shfl_down_sync(0xffffffffu, s0, off);
            s1 += __shfl_down_sync(0xffffffffu, s1, off);
            s2 += __shfl_down_sync(0xffffffffu, s2, off);
        }
        if (lane == 0) {
            float* o = out + (size_t)(row0 + r) * O_;
            o[0] = s0 + bo0;
            o[1] = s1 + bo1;
            o[2] = s2 + bo2;
        }
    }
}

// ---------------------------------------------------------------------------
// kernel_launch
// ---------------------------------------------------------------------------
extern "C" void kernel_launch(void* const* d_in, const int* in_sizes, int n_in,
                              void* d_out, int out_size)
{
    const float* inputs = (const float*)d_in[0];
    const float* W_ih   = (const float*)d_in[1];
    const float* W_hh   = (const float*)d_in[2];
    const float* b_ih   = (const float*)d_in[3];
    const float* b_hh   = (const float*)d_in[4];
    const float* h0     = (const float*)d_in[5];
    const float* W_out  = (const float*)d_in[6];
    const float* b_out  = (const float*)d_in[7];

    float* out     = (float*)d_out;                        // [B,T,O]
    float* hiddens = (float*)d_out + (size_t)B_ * T_ * O_; // [B,T,H]

    rnn_recurrent_kernel<<<B_ / 2, H_>>>(inputs, W_ih, W_hh, b_ih, b_hh, h0, hiddens);

    const int rows = B_ * T_;
    const int rows_per_block = (256 / 32) * ROWS_PER_WARP;   // 32
    const int blocks = (rows + rows_per_block - 1) / rows_per_block;  // 8192
    rnn_outproj_kernel<<<blocks, 256>>>(hiddens, W_out, b_out, out);
}

// round 14
// speedup vs baseline: 1.1022x; 1.1022x over previous
#include <cuda_runtime.h>

// Problem constants
#define B_  256
#define T_  1024
#define I_  3
#define H_  128
#define O_  3

typedef unsigned long long ull;

// ---------------------------------------------------------------------------
// Packed f32x2 helpers (Blackwell). ptxas never fuses FFMA2 from C++.
// ---------------------------------------------------------------------------
__device__ __forceinline__ ull packf2(float lo, float hi) {
    ull r;
    asm("mov.b64 %0, {%1, %2};" : "=l"(r) : "f"(lo), "f"(hi));
    return r;
}
__device__ __forceinline__ void unpackf2(ull v, float& lo, float& hi) {
    asm("mov.b64 {%0, %1}, %2;" : "=f"(lo), "=f"(hi) : "l"(v));
}
__device__ __forceinline__ ull fma2(ull a, ull b, ull c) {
    ull d;
    asm("fma.rn.f32x2 %0, %1, %2, %3;" : "=l"(d) : "l"(a), "l"(b), "l"(c));
    return d;
}

// ---------------------------------------------------------------------------
// Fast tanh: tanh(x) = 1 - 2/(1 + e^{2x}); limits exact without clamping.
// Measured end-to-end rel err ~5e-7.
// ---------------------------------------------------------------------------
__device__ __forceinline__ float fast_tanh(float x) {
    float e;
    asm("ex2.approx.f32 %0, %1;" : "=f"(e) : "f"(x * 2.885390081777927f));
    float rd;
    asm("rcp.approx.f32 %0, %1;" : "=f"(rd) : "f"(1.0f + e));
    return fmaf(-2.0f, rd, 1.0f);
}

// ---------------------------------------------------------------------------
// Recurrent kernel = the 399us winner with ONLY the K-loop changed to f32x2.
// One block per batch, one thread per hidden unit. W_hh row packed along K:
// w2[kk] = {W[j][2kk], W[j][2kk+1]} -> 64 ull = same 128 registers.
// h read as ulonglong2 (same LDS.128 count/addresses as before).
// 64 FFMA2 per thread-step instead of 128 FFMA -> half the FMA issue slots.
// ---------------------------------------------------------------------------
__global__ void __launch_bounds__(H_, 2)
rnn_recurrent_kernel(const float* __restrict__ inputs,   // [B, T, I]
                     const float* __restrict__ W_ih,     // [H, I]
                     const float* __restrict__ W_hh,     // [H, H]
                     const float* __restrict__ b_ih,     // [H]
                     const float* __restrict__ b_hh,     // [H]
                     const float* __restrict__ h0,       // [1, H]
                     float* __restrict__ hiddens)        // [B, T, H]
{
    const int b = blockIdx.x;
    const int j = threadIdx.x;

    __shared__ float hbuf[2][H_];

    // W_hh row j, packed in K-pairs -> 64 ull registers
    ull w2[H_ / 2];
    const float4* wrow = reinterpret_cast<const float4*>(W_hh + j * H_);
#pragma unroll
    for (int kk = 0; kk < H_ / 4; ++kk) {
        float4 v = wrow[kk];
        w2[2 * kk + 0] = packf2(v.x, v.y);
        w2[2 * kk + 1] = packf2(v.z, v.w);
    }

    const float wi0  = W_ih[j * I_ + 0];
    const float wi1  = W_ih[j * I_ + 1];
    const float wi2  = W_ih[j * I_ + 2];
    const float bias = b_ih[j] + b_hh[j];

    hbuf[0][j] = h0[j];

    // Anti-phase-lock skew for second-slot blocks (part of the 399us config)
    if (b >= 148) {
        float d = bias * 1e-30f;
#pragma unroll 1
        for (int i = 0; i < 75; ++i)
            d = fmaf(d, 0.999f, 1e-30f);
        if (d > 1e10f) hbuf[0][0] = d;   // never taken
    }
    __syncthreads();

    const float* inb  = inputs + (size_t)b * T_ * I_;
    float*       hout = hiddens + (size_t)b * T_ * H_;

    float x0 = inb[0], x1 = inb[1], x2 = inb[2];

    int cur = 0;
#pragma unroll 1
    for (int t = 0; t < T_; ++t) {
        // Input projection seeds the low lane of chain 0
        const float xp = fmaf(x0, wi0, fmaf(x1, wi1, fmaf(x2, wi2, bias)));
        ull A0 = packf2(xp, 0.0f);
        ull A1 = 0ull, A2 = 0ull, A3 = 0ull;

        // prefetch next x (off the critical tail)
        {
            const int tn = (t + 1 < T_) ? (t + 1) : (T_ - 1);
            const float* nx = inb + tn * I_;
            x0 = nx[0]; x1 = nx[1]; x2 = nx[2];
        }

        // h . W_hh[j,:] as 64 FFMA2 over 4 chains; h pairs straight from
        // LDS.128 (broadcast, same addresses as the scalar version).
        const ulonglong2* h2 = reinterpret_cast<const ulonglong2*>(hbuf[cur]);
#pragma unroll
        for (int kk = 0; kk < H_ / 8; ++kk) {
            const ulonglong2 p = h2[2 * kk + 0];   // {h0,h1},{h2,h3}
            const ulonglong2 q = h2[2 * kk + 1];   // {h4,h5},{h6,h7}
            A0 = fma2(p.x, w2[4 * kk + 0], A0);
            A1 = fma2(p.y, w2[4 * kk + 1], A1);
            A2 = fma2(q.x, w2[4 * kk + 2], A2);
            A3 = fma2(q.y, w2[4 * kk + 3], A3);
        }

        float s0, s1, s2, s3, s4, s5, s6, s7;
        unpackf2(A0, s0, s1);
        unpackf2(A1, s2, s3);
        unpackf2(A2, s4, s5);
        unpackf2(A3, s6, s7);
        const float acc = ((s0 + s1) + (s2 + s3)) + ((s4 + s5) + (s6 + s7));

        const float hn = fast_tanh(acc);
        const int nxt = cur ^ 1;
        hbuf[nxt][j] = hn;
        hout[t * H_ + j] = hn;
        cur = nxt;
        __syncthreads();
    }
}

// ---------------------------------------------------------------------------
// Output projection: proven config (measured 29.9us).
// ---------------------------------------------------------------------------
#define ROWS_PER_WARP 4

__global__ void __launch_bounds__(256)
rnn_outproj_kernel(const float* __restrict__ hiddens, // [B*T, H]
                   const float* __restrict__ W_out,   // [O, H]
                   const float* __restrict__ b_out,   // [O]
                   float* __restrict__ out)           // [B*T, O]
{
    const int warp = (blockIdx.x * blockDim.x + threadIdx.x) >> 5;
    const int lane = threadIdx.x & 31;
    const int row0 = warp * ROWS_PER_WARP;
    if (row0 >= B_ * T_) return;

    const float4 w0 = reinterpret_cast<const float4*>(W_out + 0 * H_)[lane];
    const float4 w1 = reinterpret_cast<const float4*>(W_out + 1 * H_)[lane];
    const float4 w2 = reinterpret_cast<const float4*>(W_out + 2 * H_)[lane];
    const float bo0 = b_out[0], bo1 = b_out[1], bo2 = b_out[2];

    float4 hv[ROWS_PER_WARP];
#pragma unroll
    for (int r = 0; r < ROWS_PER_WARP; ++r)
        hv[r] = reinterpret_cast<const float4*>(hiddens + (size_t)(row0 + r) * H_)[lane];

#pragma unroll
    for (int r = 0; r < ROWS_PER_WARP; ++r) {
        float s0 = hv[r].x * w0.x + hv[r].y * w0.y + hv[r].z * w0.z + hv[r].w * w0.w;
        float s1 = hv[r].x * w1.x + hv[r].y * w1.y + hv[r].z * w1.z + hv[r].w * w1.w;
        float s2 = hv[r].x * w2.x + hv[r].y * w2.y + hv[r].z * w2.z + hv[r].w * w2.w;
#pragma unroll
        for (int off = 16; off > 0; off >>= 1) {
            s0 += __shfl_down_sync(0xffffffffu, s0, off);
            s1 += __shfl_down_sync(0xffffffffu, s1, off);
            s2 += __shfl_down_sync(0xffffffffu, s2, off);
        }
        if (lane == 0) {
            float* o = out + (size_t)(row0 + r) * O_;
            o[0] = s0 + bo0;
            o[1] = s1 + bo1;
            o[2] = s2 + bo2;
        }
    }
}

// ---------------------------------------------------------------------------
// kernel_launch
// ---------------------------------------------------------------------------
extern "C" void kernel_launch(void* const* d_in, const int* in_sizes, int n_in,
                              void* d_out, int out_size)
{
    const float* inputs = (const float*)d_in[0];
    const float* W_ih   = (const float*)d_in[1];
    const float* W_hh   = (const float*)d_in[2];
    const float* b_ih   = (const float*)d_in[3];
    const float* b_hh   = (const float*)d_in[4];
    const float* h0     = (const float*)d_in[5];
    const float* W_out  = (const float*)d_in[6];
    const float* b_out  = (const float*)d_in[7];

    float* out     = (float*)d_out;                        // [B,T,O]
    float* hiddens = (float*)d_out + (size_t)B_ * T_ * O_; // [B,T,H]

    rnn_recurrent_kernel<<<B_, H_>>>(inputs, W_ih, W_hh, b_ih, b_hh, h0, hiddens);

    const int rows = B_ * T_;
    const int rows_per_block = (256 / 32) * ROWS_PER_WARP;            // 32
    const int blocks = (rows + rows_per_block - 1) / rows_per_block;  // 8192
    rnn_outproj_kernel<<<blocks, 256>>>(hiddens, W_out, b_out, out);
}